// round 12
// baseline (speedup 1.0000x reference)
#include <cuda_runtime.h>
#include <cuda_bf16.h>
#include <cuda_fp16.h>
#include <cstdint>
#include <math.h>

// Problem constants
#define NTOK 16384
#define DDIM 1024
#define HDIM 4096
#define NEXP 8
#define DOUT 4096
#define NSLOT (2 * NTOK)

// ---------------- scratch (no allocations allowed) ----------------
__device__ float g_ys[(size_t)NSLOT * DDIM];
__device__ float g_wgp[DDIM * NEXP + NEXP];   // W_in@W_gate + c
__device__ int   g_cnt[NEXP];
__device__ int   g_base[NEXP];
__device__ int   g_bidx[NEXP * NTOK];
__device__ int2  g_tokE[NTOK];
__device__ int2  g_tokP[NTOK];
__device__ float2 g_tokW[NTOK];

// fp16 planes
__device__ uint16_t g_x16[(size_t)NTOK * DDIM];
__device__ uint16_t g_wi16[(size_t)DDIM * DDIM];
__device__ uint16_t g_h16[(size_t)NTOK * DDIM];
__device__ uint16_t g_he16[(size_t)NSLOT * HDIM];
__device__ uint16_t g_m16[(size_t)NTOK * DDIM];
__device__ uint16_t g_w1f[(size_t)NEXP * DDIM * HDIM];
__device__ uint16_t g_w2f[(size_t)NEXP * HDIM * DDIM];
__device__ uint16_t g_whf[(size_t)DDIM * DOUT];

// ---------------- helpers ----------------
static __device__ __forceinline__ uint32_t smem_u32(const void* p) {
    uint32_t a;
    asm("{ .reg .u64 t; cvta.to.shared.u64 t, %1; cvt.u32.u64 %0, t; }"
        : "=r"(a) : "l"(p));
    return a;
}
static __device__ __forceinline__ void cp_async16(uint32_t dst, const void* src, int srcBytes) {
    asm volatile("cp.async.cg.shared.global [%0], [%1], %2, %3;"
                 :: "r"(dst), "l"(src), "n"(16), "r"(srcBytes) : "memory");
}
#define CP_COMMIT() asm volatile("cp.async.commit_group;" ::: "memory")
#define CP_WAIT(n)  asm volatile("cp.async.wait_group %0;" :: "n"(n) : "memory")

static __device__ __forceinline__ void ldsm_x4(uint32_t (&r)[4], uint32_t addr) {
    asm volatile("ldmatrix.sync.aligned.m8n8.x4.shared.b16 {%0,%1,%2,%3}, [%4];"
                 : "=r"(r[0]), "=r"(r[1]), "=r"(r[2]), "=r"(r[3]) : "r"(addr));
}
static __device__ __forceinline__ void ldsm_x4_t(uint32_t (&r)[4], uint32_t addr) {
    asm volatile("ldmatrix.sync.aligned.m8n8.x4.trans.shared.b16 {%0,%1,%2,%3}, [%4];"
                 : "=r"(r[0]), "=r"(r[1]), "=r"(r[2]), "=r"(r[3]) : "r"(addr));
}
static __device__ __forceinline__ void mma_f16(float (&d)[4],
    uint32_t a0, uint32_t a1, uint32_t a2, uint32_t a3, uint32_t b0, uint32_t b1)
{
    asm volatile("mma.sync.aligned.m16n8k16.row.col.f32.f16.f16.f32 "
                 "{%0,%1,%2,%3}, {%4,%5,%6,%7}, {%8,%9}, {%0,%1,%2,%3};"
                 : "+f"(d[0]), "+f"(d[1]), "+f"(d[2]), "+f"(d[3])
                 : "r"(a0), "r"(a1), "r"(a2), "r"(a3), "r"(b0), "r"(b1));
}

// ---------------- small kernels ----------------
__global__ void zero_i_kernel(int* p, int n) {
    int i = blockIdx.x * blockDim.x + threadIdx.x;
    if (i < n) p[i] = 0;
}
__global__ void tohalf_kernel(const float* __restrict__ src,
                              uint16_t* __restrict__ dst, long long n4)
{
    long long i = blockIdx.x * (long long)blockDim.x + threadIdx.x;
    long long stride = (long long)gridDim.x * blockDim.x;
    for (; i < n4; i += stride) {
        float4 v = reinterpret_cast<const float4*>(src)[i];
        __half2 a = __floats2half2_rn(v.x, v.y);
        __half2 b = __floats2half2_rn(v.z, v.w);
        reinterpret_cast<uint2*>(dst)[i] =
            make_uint2(*reinterpret_cast<uint32_t*>(&a),
                       *reinterpret_cast<uint32_t*>(&b));
    }
}
__global__ void prefix_kernel(const int* __restrict__ cnt, int* __restrict__ base) {
    if (threadIdx.x == 0) {
        int s = 0;
#pragma unroll
        for (int e = 0; e < NEXP; e++) { base[e] = s; s += cnt[e]; }
    }
}
__global__ void __launch_bounds__(256)
combine_kernel(const float* __restrict__ ys, const int* __restrict__ base,
               const int2* __restrict__ tokE, const int2* __restrict__ tokP,
               const float2* __restrict__ tokW, uint16_t* __restrict__ m16)
{
    const int t = blockIdx.x;
    int2 te = tokE[t];
    int2 tp = tokP[t];
    float2 tw = tokW[t];
    long long s0 = (long long)(base[te.x] + tp.x) * DDIM;
    long long s1 = (long long)(base[te.y] + tp.y) * DDIM;
    int c = threadIdx.x * 4;
    float4 y0 = *reinterpret_cast<const float4*>(ys + s0 + c);
    float4 y1 = *reinterpret_cast<const float4*>(ys + s1 + c);
    float4 v;
    v.x = tw.x * y0.x + tw.y * y1.x;
    v.y = tw.x * y0.y + tw.y * y1.y;
    v.z = tw.x * y0.z + tw.y * y1.z;
    v.w = tw.x * y0.w + tw.y * y1.w;
    __half2 a = __floats2half2_rn(v.x, v.y);
    __half2 b = __floats2half2_rn(v.z, v.w);
    long long idx = ((long long)t * DDIM + c) >> 2;
    reinterpret_cast<uint2*>(m16)[idx] =
        make_uint2(*reinterpret_cast<uint32_t*>(&a),
                   *reinterpret_cast<uint32_t*>(&b));
}

// ---------------- Wg' = W_in @ W_gate (+ c = b_in @ W_gate), exact fp32 ----------------
__global__ void __launch_bounds__(256)
wgp_kernel(const float* __restrict__ W_in, const float* __restrict__ b_in,
           const float* __restrict__ Wg, float* __restrict__ wgp)
{
    __shared__ float sWg[DDIM * 9];
    const int tid = threadIdx.x;
    for (int i = tid; i < DDIM * NEXP; i += 256)
        sWg[(i >> 3) * 9 + (i & 7)] = Wg[i];
    __syncthreads();

    const int warp = tid >> 5;
    const int lane = tid & 31;
    const int d = blockIdx.x * 8 + warp;
    if (d > DDIM) return;

    const float* row = (d < DDIM) ? W_in + (long long)d * DDIM : b_in;

    float accv[NEXP];
#pragma unroll
    for (int e = 0; e < NEXP; e++) accv[e] = 0.f;
    for (int j = lane; j < DDIM; j += 32) {
        float v = row[j];
        const float* wr = &sWg[j * 9];
#pragma unroll
        for (int e = 0; e < NEXP; e++)
            accv[e] = fmaf(v, wr[e], accv[e]);
    }
#pragma unroll
    for (int e = 0; e < NEXP; e++) {
#pragma unroll
        for (int off = 16; off > 0; off >>= 1)
            accv[e] += __shfl_xor_sync(0xffffffffu, accv[e], off);
    }
    if (lane == 0) {
#pragma unroll
        for (int e = 0; e < NEXP; e++)
            wgp[d * NEXP + e] = accv[e];
    }
}

// ---------------- gating: exact fp32 logits from x ----------------
__global__ void __launch_bounds__(256)
gate_kernel(const float* __restrict__ x, const float* __restrict__ wgp,
            int* __restrict__ cnt, int* __restrict__ bidx,
            int2* __restrict__ tokE, int2* __restrict__ tokP,
            float2* __restrict__ tokW)
{
    __shared__ float sW[DDIM * 9];
    __shared__ float sc[NEXP];
    const int tid = threadIdx.x;
    for (int i = tid; i < DDIM * NEXP; i += 256)
        sW[(i >> 3) * 9 + (i & 7)] = wgp[i];
    if (tid < NEXP) sc[tid] = wgp[DDIM * NEXP + tid];
    __syncthreads();

    const int warp = tid >> 5;
    const int lane = tid & 31;
    const int token = blockIdx.x * 8 + warp;
    if (token >= NTOK) return;

    float accv[NEXP];
#pragma unroll
    for (int e = 0; e < NEXP; e++) accv[e] = 0.f;
    const float* xrow = x + (long long)token * DDIM;
    for (int d = lane; d < DDIM; d += 32) {
        float xv = xrow[d];
        const float* wr = &sW[d * 9];
#pragma unroll
        for (int e = 0; e < NEXP; e++)
            accv[e] = fmaf(xv, wr[e], accv[e]);
    }
#pragma unroll
    for (int e = 0; e < NEXP; e++) {
#pragma unroll
        for (int off = 16; off > 0; off >>= 1)
            accv[e] += __shfl_xor_sync(0xffffffffu, accv[e], off);
    }
    if (lane == 0) {
#pragma unroll
        for (int e = 0; e < NEXP; e++) accv[e] += sc[e];
        int i1 = 0; float l1 = accv[0];
#pragma unroll
        for (int e = 1; e < NEXP; e++)
            if (accv[e] > l1) { l1 = accv[e]; i1 = e; }
        int i2 = -1; float l2 = -3.0e38f;
#pragma unroll
        for (int e = 0; e < NEXP; e++)
            if (e != i1 && accv[e] > l2) { l2 = accv[e]; i2 = e; }
        float p2 = expf(l2 - l1);
        float w1 = 1.f / (1.f + p2);
        float w2 = p2 * w1;
        int p = atomicAdd(&cnt[i1], 1);
        bidx[i1 * NTOK + p] = token;
        int q = atomicAdd(&cnt[i2], 1);
        bidx[i2 * NTOK + q] = token;
        tokE[token] = make_int2(i1, i2);
        tokP[token] = make_int2(p, q);
        tokW[token] = make_float2(w1, w2);
    }
}

// ---------------- fp16 tensor-core GEMM ----------------
// 128x128 tile, 256 threads, 2 CTAs/SM. CK=64, NBUF=3 (32KB/buf, 96KB total).
// Grid: x = row tile (fast), y = col tile, z = expert -> resident CTAs share B.
__global__ void __launch_bounds__(256, 2)
tc_gemm(const uint16_t* __restrict__ A_g, const uint16_t* __restrict__ B_g,
        size_t bStride,
        float* __restrict__ Cf, uint16_t* __restrict__ Oh,
        const float* __restrict__ bias,
        const int* __restrict__ gatherIdx,
        const int* __restrict__ cntPtr, const int* __restrict__ basePtr,
        int Mfix, int N, int K, int doRelu)
{
    extern __shared__ char smem[];

    constexpr int CK     = 64;
    constexpr int KSTEPS = 4;
    constexpr int NB     = 3;
    constexpr int PDIST  = 2;
    constexpr uint32_t ARB   = 128;     // A row bytes (64 fp16)
    constexpr uint32_t AMASK = 7;
    constexpr uint32_t BOFF  = 16384;   // A plane 16KB
    constexpr uint32_t BUFB  = 32768;   // + B plane 16KB

    const int z = blockIdx.z;
    int M = cntPtr ? __ldg(cntPtr + z) : Mfix;
    const int obase = basePtr ? __ldg(basePtr + z) : 0;
    const int row0 = blockIdx.x * 128;      // row tile on x (fast) -> B reuse
    if (row0 >= M) return;
    const int col0 = blockIdx.y * 128;

    const int tid  = threadIdx.x;
    const int lane = tid & 31;
    const int wid  = tid >> 5;      // 0..7
    const int wm   = wid >> 2;      // 0..1
    const int wn   = wid & 3;       // 0..3

    const uint32_t smem_base = smem_u32(smem);

    const uint16_t* B_e = B_g + (size_t)z * bStride;
    const float* bias_e = bias ? bias + (size_t)z * N : nullptr;
    const int* gIdx = gatherIdx ? gatherIdx + (size_t)z * NTOK : nullptr;

    // producer mapping: A 128 rows x 128B (2 thr/row x 4 units); B 64 k-rows x 256B (4 thr/row x 4 units)
    const int rA  = tid >> 1;
    const int uA0 = (tid & 1) * 4;
    const int kB  = tid >> 2;
    const int uB0 = (tid & 3) * 4;

    const int mA = row0 + rA;
    const int aOk = (mA < M) ? 16 : 0;
    const int gA = (mA < M) ? (gIdx ? gIdx[mA] : obase + mA) : 0;
    const uint16_t* aSrc = A_g + (long long)gA * K;

    const int nchunk = K / CK;

    auto prefetch = [&](int c) {
        int b = c % NB;
        int k0 = c * CK;
        uint32_t base = smem_base + b * BUFB;
#pragma unroll
        for (int p = 0; p < 4; p++) {
            int u = uA0 + p;
            uint32_t d = base + rA * ARB + ((u ^ (rA & AMASK)) << 4);
            cp_async16(d, aSrc + k0 + u * 8, aOk);
        }
#pragma unroll
        for (int p = 0; p < 4; p++) {
            int u = uB0 + p;
            uint32_t d = base + BOFF + kB * 256 + ((u ^ (kB & 7)) << 4);
            long long go = (long long)(k0 + kB) * N + col0 + u * 8;
            cp_async16(d, B_e + go, 16);
        }
        CP_COMMIT();
    };

    const int rowA  = wm * 64 + (lane & 7) + ((lane >> 3) & 1) * 8;
    const int kbA   = (lane >> 4) & 1;
    const int swzA  = rowA & AMASK;
    const int kBld  = (lane & 7) + ((lane >> 3) & 1) * 8;
    const int nbB   = (lane >> 4) & 1;
    const int kswzB = kBld & 7;

    float acc[4][4][4];
#pragma unroll
    for (int mi = 0; mi < 4; mi++)
#pragma unroll
        for (int nj = 0; nj < 4; nj++)
#pragma unroll
            for (int q = 0; q < 4; q++) acc[mi][nj][q] = 0.f;

#pragma unroll
    for (int p = 0; p < PDIST; p++) prefetch(p);

    for (int c = 0; c < nchunk; c++) {
        if (c + 1 < nchunk) { CP_WAIT(1); } else { CP_WAIT(0); }
        __syncthreads();
        if (c + PDIST < nchunk) prefetch(c + PDIST);

        const int b = c % NB;
        const uint32_t bufA = smem_base + b * BUFB;
        const uint32_t bufB = bufA + BOFF;

#pragma unroll
        for (int ks = 0; ks < KSTEPS; ks++) {
            uint32_t bh[2][4];
#pragma unroll
            for (int j = 0; j < 2; j++) {
                int nchk = wn * 4 + j * 2 + nbB;
                uint32_t boff = (uint32_t)((kBld + ks * 16) * 256 +
                                ((nchk ^ kswzB) << 4));
                ldsm_x4_t(bh[j], bufB + boff);
            }
#pragma unroll
            for (int mi = 0; mi < 4; mi++) {
                uint32_t ah[4];
                uint32_t aoff = (uint32_t)((rowA + mi * 16) * ARB +
                                (((ks * 2 + kbA) ^ swzA) << 4));
                ldsm_x4(ah, bufA + aoff);
#pragma unroll
                for (int nj = 0; nj < 4; nj++) {
                    int j = nj >> 1, p = (nj & 1) * 2;
                    mma_f16(acc[mi][nj], ah[0], ah[1], ah[2], ah[3],
                            bh[j][p], bh[j][p + 1]);
                }
            }
        }
    }

    // ---------------- epilogue ----------------
    const int colBase = col0 + wn * 32 + (lane & 3) * 2;
#pragma unroll
    for (int mi = 0; mi < 4; mi++) {
        int r0 = row0 + wm * 64 + mi * 16 + (lane >> 2);
        int r1 = r0 + 8;
#pragma unroll
        for (int nj = 0; nj < 4; nj++) {
            int col = colBase + nj * 8;
            float b0 = bias_e ? bias_e[col] : 0.f;
            float b1 = bias_e ? bias_e[col + 1] : 0.f;
            float v00 = acc[mi][nj][0] + b0;
            float v01 = acc[mi][nj][1] + b1;
            float v10 = acc[mi][nj][2] + b0;
            float v11 = acc[mi][nj][3] + b1;
            if (doRelu) {
                v00 = fmaxf(v00, 0.f); v01 = fmaxf(v01, 0.f);
                v10 = fmaxf(v10, 0.f); v11 = fmaxf(v11, 0.f);
            }
            if (r0 < M) {
                long long o = (long long)(obase + r0) * N + col;
                if (Cf) { Cf[o] = v00; Cf[o + 1] = v01; }
                if (Oh) {
                    __half2 hv = __floats2half2_rn(v00, v01);
                    *reinterpret_cast<uint32_t*>(Oh + o) =
                        *reinterpret_cast<uint32_t*>(&hv);
                }
            }
            if (r1 < M) {
                long long o = (long long)(obase + r1) * N + col;
                if (Cf) { Cf[o] = v10; Cf[o + 1] = v11; }
                if (Oh) {
                    __half2 hv = __floats2half2_rn(v10, v11);
                    *reinterpret_cast<uint32_t*>(Oh + o) =
                        *reinterpret_cast<uint32_t*>(&hv);
                }
            }
        }
    }
}

// ---------------- launch ----------------
extern "C" void kernel_launch(void* const* d_in, const int* in_sizes, int n_in,
                              void* d_out, int out_size)
{
    const float* x      = (const float*)d_in[0];
    const float* W_in   = (const float*)d_in[1];
    const float* b_in   = (const float*)d_in[2];
    const float* W_gate = (const float*)d_in[3];
    const float* W1     = (const float*)d_in[4];
    const float* b1     = (const float*)d_in[5];
    const float* W2     = (const float*)d_in[6];
    const float* b2     = (const float*)d_in[7];
    const float* W_head = (const float*)d_in[8];
    float* out = (float*)d_out;

    float *ys_p, *wgp_p;
    int *cnt_p, *base_p, *bidx_p;
    int2 *tokE_p, *tokP_p;
    float2 *tokW_p;
    uint16_t *x16, *wi16, *h16, *he16, *m16, *w1f, *w2f, *whf;
    cudaGetSymbolAddress((void**)&ys_p,  g_ys);
    cudaGetSymbolAddress((void**)&wgp_p, g_wgp);
    cudaGetSymbolAddress((void**)&cnt_p, g_cnt);
    cudaGetSymbolAddress((void**)&base_p,g_base);
    cudaGetSymbolAddress((void**)&bidx_p,g_bidx);
    cudaGetSymbolAddress((void**)&tokE_p,g_tokE);
    cudaGetSymbolAddress((void**)&tokP_p,g_tokP);
    cudaGetSymbolAddress((void**)&tokW_p,g_tokW);
    cudaGetSymbolAddress((void**)&x16,  g_x16);
    cudaGetSymbolAddress((void**)&wi16, g_wi16);
    cudaGetSymbolAddress((void**)&h16,  g_h16);
    cudaGetSymbolAddress((void**)&he16, g_he16);
    cudaGetSymbolAddress((void**)&m16,  g_m16);
    cudaGetSymbolAddress((void**)&w1f,  g_w1f);
    cudaGetSymbolAddress((void**)&w2f,  g_w2f);
    cudaGetSymbolAddress((void**)&whf,  g_whf);

    cudaFuncSetAttribute(tc_gemm,
                         cudaFuncAttributeMaxDynamicSharedMemorySize, 3 * 32768);

    tohalf_kernel<<<2048, 256>>>(x,    x16,  (long long)NTOK * DDIM / 4);      // 1
    tohalf_kernel<<<512,  256>>>(W_in, wi16, (long long)DDIM * DDIM / 4);      // 2
    zero_i_kernel<<<1, 32>>>(cnt_p, NEXP);                                     // 3

    // 4 (profiled): h16 = fp16(x16 @ wi16 + b_in)
    tc_gemm<<<dim3(NTOK / 128, DDIM / 128, 1), 256, 3 * 32768>>>(
        x16, wi16, 0,
        nullptr, h16, b_in,
        nullptr, nullptr, nullptr, NTOK, DDIM, DDIM, 0);

    // exact fp32 gate path
    wgp_kernel<<<129, 256>>>(W_in, b_in, W_gate, wgp_p);
    gate_kernel<<<NTOK / 8, 256>>>(x, wgp_p, cnt_p, bidx_p, tokE_p, tokP_p, tokW_p);
    prefix_kernel<<<1, 32>>>(cnt_p, base_p);

    tohalf_kernel<<<4096, 256>>>(W1, w1f, (long long)NEXP * DDIM * HDIM / 4);
    tohalf_kernel<<<4096, 256>>>(W2, w2f, (long long)NEXP * HDIM * DDIM / 4);
    tohalf_kernel<<<1024, 256>>>(W_head, whf, (long long)DDIM * DOUT / 4);

    // up: he16[base[e]+m] = relu(h16[bidx[e,m]] @ W1f[e] + b1[e])
    tc_gemm<<<dim3(NTOK / 128, HDIM / 128, NEXP), 256, 3 * 32768>>>(
        h16, w1f, (size_t)DDIM * HDIM,
        nullptr, he16, b1,
        bidx_p, cnt_p, base_p, 0, HDIM, DDIM, 1);

    // down: ys[base[e]+m] = he16 @ W2f[e] + b2[e]
    tc_gemm<<<dim3(NTOK / 128, DDIM / 128, NEXP), 256, 3 * 32768>>>(
        he16, w2f, (size_t)HDIM * DDIM,
        ys_p, nullptr, b2,
        nullptr, cnt_p, base_p, 0, DDIM, HDIM, 0);

    // combine -> fp16 plane for head
    combine_kernel<<<NTOK, 256>>>(ys_p, base_p, tokE_p, tokP_p, tokW_p, m16);

    // head: out = m16 @ whf
    tc_gemm<<<dim3(NTOK / 128, DOUT / 128, 1), 256, 3 * 32768>>>(
        m16, whf, 0,
        out, nullptr, nullptr,
        nullptr, nullptr, nullptr, NTOK, DOUT, DDIM, 0);
}

// round 13
// speedup vs baseline: 1.0462x; 1.0462x over previous
#include <cuda_runtime.h>
#include <cuda_bf16.h>
#include <cuda_fp16.h>
#include <cstdint>
#include <math.h>

// Problem constants
#define NTOK 16384
#define DDIM 1024
#define HDIM 4096
#define NEXP 8
#define DOUT 4096
#define NSLOT (2 * NTOK)

// ---------------- scratch (no allocations allowed) ----------------
__device__ float g_wgp[DDIM * NEXP + NEXP];   // W_in@W_gate + c
__device__ int   g_cnt[NEXP];
__device__ int   g_base[NEXP];
__device__ int   g_bidx[NEXP * NTOK];
__device__ int2  g_tokE[NTOK];
__device__ int2  g_tokP[NTOK];
__device__ float2 g_tokW[NTOK];

// fp16 planes
__device__ uint16_t g_x16[(size_t)NTOK * DDIM];
__device__ uint16_t g_wi16[(size_t)DDIM * DDIM];
__device__ uint16_t g_h16[(size_t)NTOK * DDIM];
__device__ uint16_t g_he16[(size_t)NSLOT * HDIM];
__device__ uint16_t g_ys16[(size_t)NSLOT * DDIM];
__device__ uint16_t g_m16[(size_t)NTOK * DDIM];
__device__ uint16_t g_w1f[(size_t)NEXP * DDIM * HDIM];
__device__ uint16_t g_w2f[(size_t)NEXP * HDIM * DDIM];
__device__ uint16_t g_whf[(size_t)DDIM * DOUT];

// ---------------- helpers ----------------
static __device__ __forceinline__ uint32_t smem_u32(const void* p) {
    uint32_t a;
    asm("{ .reg .u64 t; cvta.to.shared.u64 t, %1; cvt.u32.u64 %0, t; }"
        : "=r"(a) : "l"(p));
    return a;
}
static __device__ __forceinline__ void cp_async16(uint32_t dst, const void* src, int srcBytes) {
    asm volatile("cp.async.cg.shared.global [%0], [%1], %2, %3;"
                 :: "r"(dst), "l"(src), "n"(16), "r"(srcBytes) : "memory");
}
#define CP_COMMIT() asm volatile("cp.async.commit_group;" ::: "memory")
#define CP_WAIT(n)  asm volatile("cp.async.wait_group %0;" :: "n"(n) : "memory")

static __device__ __forceinline__ void ldsm_x4(uint32_t (&r)[4], uint32_t addr) {
    asm volatile("ldmatrix.sync.aligned.m8n8.x4.shared.b16 {%0,%1,%2,%3}, [%4];"
                 : "=r"(r[0]), "=r"(r[1]), "=r"(r[2]), "=r"(r[3]) : "r"(addr));
}
static __device__ __forceinline__ void ldsm_x4_t(uint32_t (&r)[4], uint32_t addr) {
    asm volatile("ldmatrix.sync.aligned.m8n8.x4.trans.shared.b16 {%0,%1,%2,%3}, [%4];"
                 : "=r"(r[0]), "=r"(r[1]), "=r"(r[2]), "=r"(r[3]) : "r"(addr));
}
static __device__ __forceinline__ void mma_f16(float (&d)[4],
    uint32_t a0, uint32_t a1, uint32_t a2, uint32_t a3, uint32_t b0, uint32_t b1)
{
    asm volatile("mma.sync.aligned.m16n8k16.row.col.f32.f16.f16.f32 "
                 "{%0,%1,%2,%3}, {%4,%5,%6,%7}, {%8,%9}, {%0,%1,%2,%3};"
                 : "+f"(d[0]), "+f"(d[1]), "+f"(d[2]), "+f"(d[3])
                 : "r"(a0), "r"(a1), "r"(a2), "r"(a3), "r"(b0), "r"(b1));
}

// ---------------- small kernels ----------------
__global__ void zero_i_kernel(int* p, int n) {
    int i = blockIdx.x * blockDim.x + threadIdx.x;
    if (i < n) p[i] = 0;
}
__global__ void tohalf_kernel(const float* __restrict__ src,
                              uint16_t* __restrict__ dst, long long n4)
{
    long long i = blockIdx.x * (long long)blockDim.x + threadIdx.x;
    long long stride = (long long)gridDim.x * blockDim.x;
    for (; i < n4; i += stride) {
        float4 v = reinterpret_cast<const float4*>(src)[i];
        __half2 a = __floats2half2_rn(v.x, v.y);
        __half2 b = __floats2half2_rn(v.z, v.w);
        reinterpret_cast<uint2*>(dst)[i] =
            make_uint2(*reinterpret_cast<uint32_t*>(&a),
                       *reinterpret_cast<uint32_t*>(&b));
    }
}
__global__ void prefix_kernel(const int* __restrict__ cnt, int* __restrict__ base) {
    if (threadIdx.x == 0) {
        int s = 0;
#pragma unroll
        for (int e = 0; e < NEXP; e++) { base[e] = s; s += cnt[e]; }
    }
}
// moe[t] = w0*y16[s0] + w1*y16[s1] -> fp16 plane for head
__global__ void __launch_bounds__(128)
combine_kernel(const uint16_t* __restrict__ ys16, const int* __restrict__ base,
               const int2* __restrict__ tokE, const int2* __restrict__ tokP,
               const float2* __restrict__ tokW, uint16_t* __restrict__ m16)
{
    const int t = blockIdx.x;
    int2 te = tokE[t];
    int2 tp = tokP[t];
    float2 tw = tokW[t];
    long long s0 = (long long)(base[te.x] + tp.x) * DDIM;
    long long s1 = (long long)(base[te.y] + tp.y) * DDIM;
    int c = threadIdx.x * 8;
    uint4 y0 = *reinterpret_cast<const uint4*>(ys16 + s0 + c);
    uint4 y1 = *reinterpret_cast<const uint4*>(ys16 + s1 + c);
    __half2 w0 = __float2half2_rn(tw.x);
    __half2 w1 = __float2half2_rn(tw.y);
    uint4 o;
    const __half2* p0 = reinterpret_cast<const __half2*>(&y0);
    const __half2* p1 = reinterpret_cast<const __half2*>(&y1);
    __half2* po = reinterpret_cast<__half2*>(&o);
#pragma unroll
    for (int j = 0; j < 4; j++)
        po[j] = __hfma2(w0, p0[j], __hmul2(w1, p1[j]));
    *reinterpret_cast<uint4*>(m16 + (long long)t * DDIM + c) = o;
}

// ---------------- Wg' = W_in @ W_gate (+ c = b_in @ W_gate), exact fp32 ----------------
__global__ void __launch_bounds__(256)
wgp_kernel(const float* __restrict__ W_in, const float* __restrict__ b_in,
           const float* __restrict__ Wg, float* __restrict__ wgp)
{
    __shared__ float sWg[DDIM * 9];
    const int tid = threadIdx.x;
    for (int i = tid; i < DDIM * NEXP; i += 256)
        sWg[(i >> 3) * 9 + (i & 7)] = Wg[i];
    __syncthreads();

    const int warp = tid >> 5;
    const int lane = tid & 31;
    const int d = blockIdx.x * 8 + warp;
    if (d > DDIM) return;

    const float* row = (d < DDIM) ? W_in + (long long)d * DDIM : b_in;

    float accv[NEXP];
#pragma unroll
    for (int e = 0; e < NEXP; e++) accv[e] = 0.f;
    for (int j = lane; j < DDIM; j += 32) {
        float v = row[j];
        const float* wr = &sWg[j * 9];
#pragma unroll
        for (int e = 0; e < NEXP; e++)
            accv[e] = fmaf(v, wr[e], accv[e]);
    }
#pragma unroll
    for (int e = 0; e < NEXP; e++) {
#pragma unroll
        for (int off = 16; off > 0; off >>= 1)
            accv[e] += __shfl_xor_sync(0xffffffffu, accv[e], off);
    }
    if (lane == 0) {
#pragma unroll
        for (int e = 0; e < NEXP; e++)
            wgp[d * NEXP + e] = accv[e];
    }
}

// ---------------- gating: exact fp32 logits from x ----------------
__global__ void __launch_bounds__(256)
gate_kernel(const float* __restrict__ x, const float* __restrict__ wgp,
            int* __restrict__ cnt, int* __restrict__ bidx,
            int2* __restrict__ tokE, int2* __restrict__ tokP,
            float2* __restrict__ tokW)
{
    __shared__ float sW[DDIM * 9];
    __shared__ float sc[NEXP];
    const int tid = threadIdx.x;
    for (int i = tid; i < DDIM * NEXP; i += 256)
        sW[(i >> 3) * 9 + (i & 7)] = wgp[i];
    if (tid < NEXP) sc[tid] = wgp[DDIM * NEXP + tid];
    __syncthreads();

    const int warp = tid >> 5;
    const int lane = tid & 31;
    const int token = blockIdx.x * 8 + warp;
    if (token >= NTOK) return;

    float accv[NEXP];
#pragma unroll
    for (int e = 0; e < NEXP; e++) accv[e] = 0.f;
    const float* xrow = x + (long long)token * DDIM;
    for (int d = lane; d < DDIM; d += 32) {
        float xv = xrow[d];
        const float* wr = &sW[d * 9];
#pragma unroll
        for (int e = 0; e < NEXP; e++)
            accv[e] = fmaf(xv, wr[e], accv[e]);
    }
#pragma unroll
    for (int e = 0; e < NEXP; e++) {
#pragma unroll
        for (int off = 16; off > 0; off >>= 1)
            accv[e] += __shfl_xor_sync(0xffffffffu, accv[e], off);
    }
    if (lane == 0) {
#pragma unroll
        for (int e = 0; e < NEXP; e++) accv[e] += sc[e];
        int i1 = 0; float l1 = accv[0];
#pragma unroll
        for (int e = 1; e < NEXP; e++)
            if (accv[e] > l1) { l1 = accv[e]; i1 = e; }
        int i2 = -1; float l2 = -3.0e38f;
#pragma unroll
        for (int e = 0; e < NEXP; e++)
            if (e != i1 && accv[e] > l2) { l2 = accv[e]; i2 = e; }
        float p2 = expf(l2 - l1);
        float w1 = 1.f / (1.f + p2);
        float w2 = p2 * w1;
        int p = atomicAdd(&cnt[i1], 1);
        bidx[i1 * NTOK + p] = token;
        int q = atomicAdd(&cnt[i2], 1);
        bidx[i2 * NTOK + q] = token;
        tokE[token] = make_int2(i1, i2);
        tokP[token] = make_int2(p, q);
        tokW[token] = make_float2(w1, w2);
    }
}

// ---------------- fp16 tensor-core GEMM: 256x128 tile, 512 threads, CK=64 ----------------
__global__ void __launch_bounds__(512, 1)
tc_gemm(const uint16_t* __restrict__ A_g, const uint16_t* __restrict__ B_g,
        size_t bStride,
        float* __restrict__ Cf, uint16_t* __restrict__ Oh,
        const float* __restrict__ bias,
        const int* __restrict__ gatherIdx,
        const int* __restrict__ cntPtr, const int* __restrict__ basePtr,
        int Mfix, int N, int K, int doRelu)
{
    extern __shared__ char smem[];

    constexpr int CK     = 64;
    constexpr int KSTEPS = 4;
    constexpr int NB     = 3;
    constexpr int PDIST  = 2;
    constexpr uint32_t ARB   = 128;     // A row bytes
    constexpr uint32_t AMASK = 7;
    constexpr uint32_t BOFF  = 32768;   // A region 32KB
    constexpr uint32_t BUFB  = 49152;   // + B 16KB

    const int z = blockIdx.z;
    int M = cntPtr ? __ldg(cntPtr + z) : Mfix;
    const int obase = basePtr ? __ldg(basePtr + z) : 0;
    const int row0 = blockIdx.y * 256;
    if (row0 >= M) return;
    const int col0 = blockIdx.x * 128;

    const int tid  = threadIdx.x;
    const int lane = tid & 31;
    const int wid  = tid >> 5;
    const int wm   = wid >> 2;
    const int wn   = wid & 3;

    const uint32_t smem_base = smem_u32(smem);

    const uint16_t* B_e = B_g + (size_t)z * bStride;
    const float* bias_e = bias ? bias + (size_t)z * N : nullptr;
    const int* gIdx = gatherIdx ? gatherIdx + (size_t)z * NTOK : nullptr;

    // producer mapping
    const int rA  = tid >> 1;          // 0..255
    const int uA0 = (tid & 1) * 4;
    const int kB  = tid >> 3;          // 0..63
    const int uB0 = (tid & 7) * 2;

    const int mA = row0 + rA;
    const int aOk = (mA < M) ? 16 : 0;
    const int gA = (mA < M) ? (gIdx ? gIdx[mA] : obase + mA) : 0;
    const uint16_t* aSrc = A_g + (long long)gA * K;

    const int nchunk = K / CK;

    auto prefetch = [&](int c) {
        int b = c % NB;
        int k0 = c * CK;
        uint32_t base = smem_base + b * BUFB;
#pragma unroll
        for (int p = 0; p < 4; p++) {
            int u = uA0 + p;
            uint32_t d = base + rA * ARB + ((u ^ (rA & AMASK)) << 4);
            cp_async16(d, aSrc + k0 + u * 8, aOk);
        }
#pragma unroll
        for (int p = 0; p < 2; p++) {
            int u = uB0 + p;
            uint32_t d = base + BOFF + kB * 256 + ((u ^ (kB & 7)) << 4);
            long long go = (long long)(k0 + kB) * N + col0 + u * 8;
            cp_async16(d, B_e + go, 16);
        }
        CP_COMMIT();
    };

    const int rowA  = wm * 64 + (lane & 7) + ((lane >> 3) & 1) * 8;
    const int kbA   = (lane >> 4) & 1;
    const int swzA  = rowA & AMASK;
    const int kBld  = (lane & 7) + ((lane >> 3) & 1) * 8;
    const int nbB   = (lane >> 4) & 1;
    const int kswzB = kBld & 7;

    float acc[4][4][4];
#pragma unroll
    for (int mi = 0; mi < 4; mi++)
#pragma unroll
        for (int nj = 0; nj < 4; nj++)
#pragma unroll
            for (int q = 0; q < 4; q++) acc[mi][nj][q] = 0.f;

#pragma unroll
    for (int p = 0; p < PDIST; p++) prefetch(p);

    for (int c = 0; c < nchunk; c++) {
        if (c + 1 < nchunk) { CP_WAIT(1); } else { CP_WAIT(0); }
        __syncthreads();
        if (c + PDIST < nchunk) prefetch(c + PDIST);

        const int b = c % NB;
        const uint32_t bufA = smem_base + b * BUFB;
        const uint32_t bufB = bufA + BOFF;

#pragma unroll
        for (int ks = 0; ks < KSTEPS; ks++) {
            uint32_t bh[2][4];
#pragma unroll
            for (int j = 0; j < 2; j++) {
                int nchk = wn * 4 + j * 2 + nbB;
                uint32_t boff = (uint32_t)((kBld + ks * 16) * 256 +
                                ((nchk ^ kswzB) << 4));
                ldsm_x4_t(bh[j], bufB + boff);
            }
#pragma unroll
            for (int mi = 0; mi < 4; mi++) {
                uint32_t ah[4];
                uint32_t aoff = (uint32_t)((rowA + mi * 16) * ARB +
                                (((ks * 2 + kbA) ^ swzA) << 4));
                ldsm_x4(ah, bufA + aoff);
#pragma unroll
                for (int nj = 0; nj < 4; nj++) {
                    int j = nj >> 1, p = (nj & 1) * 2;
                    mma_f16(acc[mi][nj], ah[0], ah[1], ah[2], ah[3],
                            bh[j][p], bh[j][p + 1]);
                }
            }
        }
    }

    // ---------------- epilogue ----------------
    const int colBase = col0 + wn * 32 + (lane & 3) * 2;
#pragma unroll
    for (int mi = 0; mi < 4; mi++) {
        int r0 = row0 + wm * 64 + mi * 16 + (lane >> 2);
        int r1 = r0 + 8;
#pragma unroll
        for (int nj = 0; nj < 4; nj++) {
            int col = colBase + nj * 8;
            float b0 = bias_e ? bias_e[col] : 0.f;
            float b1 = bias_e ? bias_e[col + 1] : 0.f;
            float v00 = acc[mi][nj][0] + b0;
            float v01 = acc[mi][nj][1] + b1;
            float v10 = acc[mi][nj][2] + b0;
            float v11 = acc[mi][nj][3] + b1;
            if (doRelu) {
                v00 = fmaxf(v00, 0.f); v01 = fmaxf(v01, 0.f);
                v10 = fmaxf(v10, 0.f); v11 = fmaxf(v11, 0.f);
            }
            if (r0 < M) {
                long long o = (long long)(obase + r0) * N + col;
                if (Cf) { Cf[o] = v00; Cf[o + 1] = v01; }
                if (Oh) {
                    __half2 hv = __floats2half2_rn(v00, v01);
                    *reinterpret_cast<uint32_t*>(Oh + o) =
                        *reinterpret_cast<uint32_t*>(&hv);
                }
            }
            if (r1 < M) {
                long long o = (long long)(obase + r1) * N + col;
                if (Cf) { Cf[o] = v10; Cf[o + 1] = v11; }
                if (Oh) {
                    __half2 hv = __floats2half2_rn(v10, v11);
                    *reinterpret_cast<uint32_t*>(Oh + o) =
                        *reinterpret_cast<uint32_t*>(&hv);
                }
            }
        }
    }
}

// ---------------- launch ----------------
extern "C" void kernel_launch(void* const* d_in, const int* in_sizes, int n_in,
                              void* d_out, int out_size)
{
    const float* x      = (const float*)d_in[0];
    const float* W_in   = (const float*)d_in[1];
    const float* b_in   = (const float*)d_in[2];
    const float* W_gate = (const float*)d_in[3];
    const float* W1     = (const float*)d_in[4];
    const float* b1     = (const float*)d_in[5];
    const float* W2     = (const float*)d_in[6];
    const float* b2     = (const float*)d_in[7];
    const float* W_head = (const float*)d_in[8];
    float* out = (float*)d_out;

    float *wgp_p;
    int *cnt_p, *base_p, *bidx_p;
    int2 *tokE_p, *tokP_p;
    float2 *tokW_p;
    uint16_t *x16, *wi16, *h16, *he16, *ys16, *m16, *w1f, *w2f, *whf;
    cudaGetSymbolAddress((void**)&wgp_p, g_wgp);
    cudaGetSymbolAddress((void**)&cnt_p, g_cnt);
    cudaGetSymbolAddress((void**)&base_p,g_base);
    cudaGetSymbolAddress((void**)&bidx_p,g_bidx);
    cudaGetSymbolAddress((void**)&tokE_p,g_tokE);
    cudaGetSymbolAddress((void**)&tokP_p,g_tokP);
    cudaGetSymbolAddress((void**)&tokW_p,g_tokW);
    cudaGetSymbolAddress((void**)&x16,  g_x16);
    cudaGetSymbolAddress((void**)&wi16, g_wi16);
    cudaGetSymbolAddress((void**)&h16,  g_h16);
    cudaGetSymbolAddress((void**)&he16, g_he16);
    cudaGetSymbolAddress((void**)&ys16, g_ys16);
    cudaGetSymbolAddress((void**)&m16,  g_m16);
    cudaGetSymbolAddress((void**)&w1f,  g_w1f);
    cudaGetSymbolAddress((void**)&w2f,  g_w2f);
    cudaGetSymbolAddress((void**)&whf,  g_whf);

    cudaFuncSetAttribute(tc_gemm,
                         cudaFuncAttributeMaxDynamicSharedMemorySize, 3 * 49152);

    tohalf_kernel<<<2048, 256>>>(x,    x16,  (long long)NTOK * DDIM / 4);      // 1
    tohalf_kernel<<<512,  256>>>(W_in, wi16, (long long)DDIM * DDIM / 4);      // 2
    zero_i_kernel<<<1, 32>>>(cnt_p, NEXP);                                     // 3

    // 4 (profiled): h16 = fp16(x16 @ wi16 + b_in)
    tc_gemm<<<dim3(DDIM / 128, NTOK / 256, 1), 512, 3 * 49152>>>(
        x16, wi16, 0,
        nullptr, h16, b_in,
        nullptr, nullptr, nullptr, NTOK, DDIM, DDIM, 0);

    // exact fp32 gate path: Wg' = W_in@W_gate, c = b_in@W_gate
    wgp_kernel<<<129, 256>>>(W_in, b_in, W_gate, wgp_p);
    gate_kernel<<<NTOK / 8, 256>>>(x, wgp_p, cnt_p, bidx_p, tokE_p, tokP_p, tokW_p);
    prefix_kernel<<<1, 32>>>(cnt_p, base_p);

    tohalf_kernel<<<4096, 256>>>(W1, w1f, (long long)NEXP * DDIM * HDIM / 4);
    tohalf_kernel<<<4096, 256>>>(W2, w2f, (long long)NEXP * HDIM * DDIM / 4);
    tohalf_kernel<<<1024, 256>>>(W_head, whf, (long long)DDIM * DOUT / 4);

    // up: he16[base[e]+m] = relu(h16[bidx[e,m]] @ W1f[e] + b1[e])
    tc_gemm<<<dim3(HDIM / 128, NTOK / 256, NEXP), 512, 3 * 49152>>>(
        h16, w1f, (size_t)DDIM * HDIM,
        nullptr, he16, b1,
        bidx_p, cnt_p, base_p, 0, HDIM, DDIM, 1);

    // down: ys16[base[e]+m] = fp16(he16 @ W2f[e] + b2[e])
    tc_gemm<<<dim3(DDIM / 128, NTOK / 256, NEXP), 512, 3 * 49152>>>(
        he16, w2f, (size_t)HDIM * DDIM,
        nullptr, ys16, b2,
        nullptr, cnt_p, base_p, 0, DDIM, HDIM, 0);

    // combine (fp16 in/out) -> m16 for head
    combine_kernel<<<NTOK, 128>>>(ys16, base_p, tokE_p, tokP_p, tokW_p, m16);

    // head: out = m16 @ whf
    tc_gemm<<<dim3(DOUT / 128, NTOK / 256, 1), 512, 3 * 49152>>>(
        m16, whf, 0,
        out, nullptr, nullptr,
        nullptr, nullptr, nullptr, NTOK, DOUT, DDIM, 0);
}

// round 14
// speedup vs baseline: 1.1406x; 1.0902x over previous
#include <cuda_runtime.h>
#include <cuda_bf16.h>
#include <cuda_fp16.h>
#include <cstdint>
#include <math.h>

// Problem constants
#define NTOK 16384
#define DDIM 1024
#define HDIM 4096
#define NEXP 8
#define DOUT 4096
#define NSLOT (2 * NTOK)

// ---------------- scratch (no allocations allowed) ----------------
__device__ float g_wgp[DDIM * NEXP + NEXP];   // W_in@W_gate + c
__device__ int   g_cnt[NEXP];
__device__ int   g_base[NEXP];
__device__ int   g_bidx[NEXP * NTOK];
__device__ int2  g_tokE[NTOK];
__device__ int2  g_tokP[NTOK];
__device__ float2 g_tokW[NTOK];

// fp16 planes
__device__ uint16_t g_x16[(size_t)NTOK * DDIM];
__device__ uint16_t g_wi16[(size_t)DDIM * DDIM];
__device__ uint16_t g_h16[(size_t)NTOK * DDIM];
__device__ uint16_t g_he16[(size_t)NSLOT * HDIM];
__device__ uint16_t g_ys16[(size_t)NSLOT * DDIM];
__device__ uint16_t g_m16[(size_t)NTOK * DDIM];
__device__ uint16_t g_w1f[(size_t)NEXP * DDIM * HDIM];
__device__ uint16_t g_w2f[(size_t)NEXP * HDIM * DDIM];
__device__ uint16_t g_whf[(size_t)DDIM * DOUT];

// ---------------- helpers ----------------
static __device__ __forceinline__ uint32_t smem_u32(const void* p) {
    uint32_t a;
    asm("{ .reg .u64 t; cvta.to.shared.u64 t, %1; cvt.u32.u64 %0, t; }"
        : "=r"(a) : "l"(p));
    return a;
}
static __device__ __forceinline__ void cp_async16(uint32_t dst, const void* src, int srcBytes) {
    asm volatile("cp.async.cg.shared.global [%0], [%1], %2, %3;"
                 :: "r"(dst), "l"(src), "n"(16), "r"(srcBytes) : "memory");
}
#define CP_COMMIT() asm volatile("cp.async.commit_group;" ::: "memory")
#define CP_WAIT(n)  asm volatile("cp.async.wait_group %0;" :: "n"(n) : "memory")

#define MBAR_INIT(addr, cnt) \
    asm volatile("mbarrier.init.shared.b64 [%0], %1;" :: "r"(addr), "r"(cnt) : "memory")
#define MBAR_ARRIVE(addr) \
    asm volatile("mbarrier.arrive.shared.b64 _, [%0];" :: "r"(addr) : "memory")
#define MBAR_WAIT(addr, par) do {                                                   \
    uint32_t _m = (addr); uint32_t _p = (par); uint32_t _done;                      \
    asm volatile("{\n\t.reg .pred p;\n\t"                                           \
        "mbarrier.try_wait.parity.acquire.cta.shared::cta.b64 p, [%1], %2;\n\t"     \
        "selp.b32 %0, 1, 0, p;\n\t}" : "=r"(_done) : "r"(_m), "r"(_p) : "memory");  \
    if (!_done) {                                                                    \
        asm volatile("{\n\t.reg .pred P1;\n\t"                                      \
            "WL_%=:\n\t"                                                            \
            "mbarrier.try_wait.parity.acquire.cta.shared::cta.b64 P1, [%0], %1, 0x989680;\n\t" \
            "@P1 bra.uni WD_%=;\n\t"                                                \
            "bra.uni WL_%=;\n\t"                                                    \
            "WD_%=:\n\t}" :: "r"(_m), "r"(_p) : "memory");                          \
    }                                                                                \
} while (0)

static __device__ __forceinline__ void ldsm_x4(uint32_t (&r)[4], uint32_t addr) {
    asm volatile("ldmatrix.sync.aligned.m8n8.x4.shared.b16 {%0,%1,%2,%3}, [%4];"
                 : "=r"(r[0]), "=r"(r[1]), "=r"(r[2]), "=r"(r[3]) : "r"(addr));
}
static __device__ __forceinline__ void ldsm_x4_t(uint32_t (&r)[4], uint32_t addr) {
    asm volatile("ldmatrix.sync.aligned.m8n8.x4.trans.shared.b16 {%0,%1,%2,%3}, [%4];"
                 : "=r"(r[0]), "=r"(r[1]), "=r"(r[2]), "=r"(r[3]) : "r"(addr));
}
static __device__ __forceinline__ void mma_f16(float (&d)[4],
    uint32_t a0, uint32_t a1, uint32_t a2, uint32_t a3, uint32_t b0, uint32_t b1)
{
    asm volatile("mma.sync.aligned.m16n8k16.row.col.f32.f16.f16.f32 "
                 "{%0,%1,%2,%3}, {%4,%5,%6,%7}, {%8,%9}, {%0,%1,%2,%3};"
                 : "+f"(d[0]), "+f"(d[1]), "+f"(d[2]), "+f"(d[3])
                 : "r"(a0), "r"(a1), "r"(a2), "r"(a3), "r"(b0), "r"(b1));
}

// ---------------- small kernels ----------------
__global__ void zero_i_kernel(int* p, int n) {
    int i = blockIdx.x * blockDim.x + threadIdx.x;
    if (i < n) p[i] = 0;
}
__global__ void tohalf_kernel(const float* __restrict__ src,
                              uint16_t* __restrict__ dst, long long n4)
{
    long long i = blockIdx.x * (long long)blockDim.x + threadIdx.x;
    long long stride = (long long)gridDim.x * blockDim.x;
    for (; i < n4; i += stride) {
        float4 v = reinterpret_cast<const float4*>(src)[i];
        __half2 a = __floats2half2_rn(v.x, v.y);
        __half2 b = __floats2half2_rn(v.z, v.w);
        reinterpret_cast<uint2*>(dst)[i] =
            make_uint2(*reinterpret_cast<uint32_t*>(&a),
                       *reinterpret_cast<uint32_t*>(&b));
    }
}
__global__ void prefix_kernel(const int* __restrict__ cnt, int* __restrict__ base) {
    if (threadIdx.x == 0) {
        int s = 0;
#pragma unroll
        for (int e = 0; e < NEXP; e++) { base[e] = s; s += cnt[e]; }
    }
}
__global__ void __launch_bounds__(128)
combine_kernel(const uint16_t* __restrict__ ys16, const int* __restrict__ base,
               const int2* __restrict__ tokE, const int2* __restrict__ tokP,
               const float2* __restrict__ tokW, uint16_t* __restrict__ m16)
{
    const int t = blockIdx.x;
    int2 te = tokE[t];
    int2 tp = tokP[t];
    float2 tw = tokW[t];
    long long s0 = (long long)(base[te.x] + tp.x) * DDIM;
    long long s1 = (long long)(base[te.y] + tp.y) * DDIM;
    int c = threadIdx.x * 8;
    uint4 y0 = *reinterpret_cast<const uint4*>(ys16 + s0 + c);
    uint4 y1 = *reinterpret_cast<const uint4*>(ys16 + s1 + c);
    __half2 w0 = __float2half2_rn(tw.x);
    __half2 w1 = __float2half2_rn(tw.y);
    uint4 o;
    const __half2* p0 = reinterpret_cast<const __half2*>(&y0);
    const __half2* p1 = reinterpret_cast<const __half2*>(&y1);
    __half2* po = reinterpret_cast<__half2*>(&o);
#pragma unroll
    for (int j = 0; j < 4; j++)
        po[j] = __hfma2(w0, p0[j], __hmul2(w1, p1[j]));
    *reinterpret_cast<uint4*>(m16 + (long long)t * DDIM + c) = o;
}

// ---------------- Wg' = W_in @ W_gate (+ c = b_in @ W_gate), exact fp32 ----------------
__global__ void __launch_bounds__(256)
wgp_kernel(const float* __restrict__ W_in, const float* __restrict__ b_in,
           const float* __restrict__ Wg, float* __restrict__ wgp)
{
    __shared__ float sWg[DDIM * 9];
    const int tid = threadIdx.x;
    for (int i = tid; i < DDIM * NEXP; i += 256)
        sWg[(i >> 3) * 9 + (i & 7)] = Wg[i];
    __syncthreads();

    const int warp = tid >> 5;
    const int lane = tid & 31;
    const int d = blockIdx.x * 8 + warp;
    if (d > DDIM) return;

    const float* row = (d < DDIM) ? W_in + (long long)d * DDIM : b_in;

    float accv[NEXP];
#pragma unroll
    for (int e = 0; e < NEXP; e++) accv[e] = 0.f;
    for (int j = lane; j < DDIM; j += 32) {
        float v = row[j];
        const float* wr = &sWg[j * 9];
#pragma unroll
        for (int e = 0; e < NEXP; e++)
            accv[e] = fmaf(v, wr[e], accv[e]);
    }
#pragma unroll
    for (int e = 0; e < NEXP; e++) {
#pragma unroll
        for (int off = 16; off > 0; off >>= 1)
            accv[e] += __shfl_xor_sync(0xffffffffu, accv[e], off);
    }
    if (lane == 0) {
#pragma unroll
        for (int e = 0; e < NEXP; e++)
            wgp[d * NEXP + e] = accv[e];
    }
}

// ---------------- gating: exact fp32 logits from x ----------------
__global__ void __launch_bounds__(256)
gate_kernel(const float* __restrict__ x, const float* __restrict__ wgp,
            int* __restrict__ cnt, int* __restrict__ bidx,
            int2* __restrict__ tokE, int2* __restrict__ tokP,
            float2* __restrict__ tokW)
{
    __shared__ float sW[DDIM * 9];
    __shared__ float sc[NEXP];
    const int tid = threadIdx.x;
    for (int i = tid; i < DDIM * NEXP; i += 256)
        sW[(i >> 3) * 9 + (i & 7)] = wgp[i];
    if (tid < NEXP) sc[tid] = wgp[DDIM * NEXP + tid];
    __syncthreads();

    const int warp = tid >> 5;
    const int lane = tid & 31;
    const int token = blockIdx.x * 8 + warp;
    if (token >= NTOK) return;

    float accv[NEXP];
#pragma unroll
    for (int e = 0; e < NEXP; e++) accv[e] = 0.f;
    const float* xrow = x + (long long)token * DDIM;
    for (int d = lane; d < DDIM; d += 32) {
        float xv = xrow[d];
        const float* wr = &sW[d * 9];
#pragma unroll
        for (int e = 0; e < NEXP; e++)
            accv[e] = fmaf(xv, wr[e], accv[e]);
    }
#pragma unroll
    for (int e = 0; e < NEXP; e++) {
#pragma unroll
        for (int off = 16; off > 0; off >>= 1)
            accv[e] += __shfl_xor_sync(0xffffffffu, accv[e], off);
    }
    if (lane == 0) {
#pragma unroll
        for (int e = 0; e < NEXP; e++) accv[e] += sc[e];
        int i1 = 0; float l1 = accv[0];
#pragma unroll
        for (int e = 1; e < NEXP; e++)
            if (accv[e] > l1) { l1 = accv[e]; i1 = e; }
        int i2 = -1; float l2 = -3.0e38f;
#pragma unroll
        for (int e = 0; e < NEXP; e++)
            if (e != i1 && accv[e] > l2) { l2 = accv[e]; i2 = e; }
        float p2 = expf(l2 - l1);
        float w1 = 1.f / (1.f + p2);
        float w2 = p2 * w1;
        int p = atomicAdd(&cnt[i1], 1);
        bidx[i1 * NTOK + p] = token;
        int q = atomicAdd(&cnt[i2], 1);
        bidx[i2 * NTOK + q] = token;
        tokE[token] = make_int2(i1, i2);
        tokP[token] = make_int2(p, q);
        tokW[token] = make_float2(w1, w2);
    }
}

// ---------------- fp16 tensor-core GEMM: 256x128 tile, 512 threads, CK=64 ----------------
// mbarrier producer/consumer ring (NB=4) instead of per-chunk __syncthreads.
__global__ void __launch_bounds__(512, 1)
tc_gemm(const uint16_t* __restrict__ A_g, const uint16_t* __restrict__ B_g,
        size_t bStride,
        float* __restrict__ Cf, uint16_t* __restrict__ Oh,
        const float* __restrict__ bias,
        const int* __restrict__ gatherIdx,
        const int* __restrict__ cntPtr, const int* __restrict__ basePtr,
        int Mfix, int N, int K, int doRelu)
{
    extern __shared__ char smem[];

    constexpr int CK     = 64;
    constexpr int KSTEPS = 4;
    constexpr int NB     = 4;
    constexpr uint32_t ARB   = 128;     // A row bytes
    constexpr uint32_t AMASK = 7;
    constexpr uint32_t BOFF  = 32768;   // A region 32KB
    constexpr uint32_t BUFB  = 49152;   // + B 16KB
    // smem: [0..31] full mbarriers (4x8), [32..63] empty mbarriers, buffers @1024
    #define SMEM_GEMM_TOTAL (1024 + 4 * 49152)

    const int z = blockIdx.z;
    int M = cntPtr ? __ldg(cntPtr + z) : Mfix;
    const int obase = basePtr ? __ldg(basePtr + z) : 0;
    const int row0 = blockIdx.y * 256;
    if (row0 >= M) return;
    const int col0 = blockIdx.x * 128;

    const int tid  = threadIdx.x;
    const int lane = tid & 31;
    const int wid  = tid >> 5;
    const int wm   = wid >> 2;
    const int wn   = wid & 3;

    const uint32_t smem_base = smem_u32(smem);
    const uint32_t mb_full  = smem_base;
    const uint32_t mb_empty = smem_base + 32;
    const uint32_t tiles    = smem_base + 1024;

    if (tid == 0) {
#pragma unroll
        for (int b = 0; b < NB; b++) {
            MBAR_INIT(mb_full + b * 8, 16);
            MBAR_INIT(mb_empty + b * 8, 16);
        }
    }
    __syncthreads();

    const uint16_t* B_e = B_g + (size_t)z * bStride;
    const float* bias_e = bias ? bias + (size_t)z * N : nullptr;
    const int* gIdx = gatherIdx ? gatherIdx + (size_t)z * NTOK : nullptr;

    // producer mapping
    const int rA  = tid >> 1;          // 0..255
    const int uA0 = (tid & 1) * 4;
    const int kB  = tid >> 3;          // 0..63
    const int uB0 = (tid & 7) * 2;

    const int mA = row0 + rA;
    const int aOk = (mA < M) ? 16 : 0;
    const int gA = (mA < M) ? (gIdx ? gIdx[mA] : obase + mA) : 0;
    const uint16_t* aSrc = A_g + (long long)gA * K;

    const int nchunk = K / CK;

    auto copies = [&](int c) {
        int b = c % NB;
        int k0 = c * CK;
        uint32_t base = tiles + b * BUFB;
#pragma unroll
        for (int p = 0; p < 4; p++) {
            int u = uA0 + p;
            uint32_t d = base + rA * ARB + ((u ^ (rA & AMASK)) << 4);
            cp_async16(d, aSrc + k0 + u * 8, aOk);
        }
#pragma unroll
        for (int p = 0; p < 2; p++) {
            int u = uB0 + p;
            uint32_t d = base + BOFF + kB * 256 + ((u ^ (kB & 7)) << 4);
            long long go = (long long)(k0 + kB) * N + col0 + u * 8;
            cp_async16(d, B_e + go, 16);
        }
    };

    const int rowA  = wm * 64 + (lane & 7) + ((lane >> 3) & 1) * 8;
    const int kbA   = (lane >> 4) & 1;
    const int swzA  = rowA & AMASK;
    const int kBld  = (lane & 7) + ((lane >> 3) & 1) * 8;
    const int nbB   = (lane >> 4) & 1;
    const int kswzB = kBld & 7;

    float acc[4][4][4];
#pragma unroll
    for (int mi = 0; mi < 4; mi++)
#pragma unroll
        for (int nj = 0; nj < 4; nj++)
#pragma unroll
            for (int q = 0; q < 4; q++) acc[mi][nj][q] = 0.f;

    // prologue: prefetch chunks 0 and 1 (buffers fresh, no empty-wait)
    copies(0); CP_COMMIT();
    copies(1); CP_COMMIT();

    for (int c = 0; c < nchunk; c++) {
        // prefetch chunk c+2 (wait for buffer free if it was used by chunk c+2-NB)
        int p = c + 2;
        if (p < nchunk) {
            if (p >= NB) MBAR_WAIT(mb_empty + (p % NB) * 8, ((p - NB) / NB) & 1);
            copies(p);
        }
        CP_COMMIT();
        CP_WAIT(2);                      // own copies for chunk c are complete
        if (lane == 0) MBAR_ARRIVE(mb_full + (c % NB) * 8);
        MBAR_WAIT(mb_full + (c % NB) * 8, (c / NB) & 1);

        const int b = c % NB;
        const uint32_t bufA = tiles + b * BUFB;
        const uint32_t bufB = bufA + BOFF;

#pragma unroll
        for (int ks = 0; ks < KSTEPS; ks++) {
            uint32_t bh[2][4];
#pragma unroll
            for (int j = 0; j < 2; j++) {
                int nchk = wn * 4 + j * 2 + nbB;
                uint32_t boff = (uint32_t)((kBld + ks * 16) * 256 +
                                ((nchk ^ kswzB) << 4));
                ldsm_x4_t(bh[j], bufB + boff);
            }
#pragma unroll
            for (int mi = 0; mi < 4; mi++) {
                uint32_t ah[4];
                uint32_t aoff = (uint32_t)((rowA + mi * 16) * ARB +
                                (((ks * 2 + kbA) ^ swzA) << 4));
                ldsm_x4(ah, bufA + aoff);
#pragma unroll
                for (int nj = 0; nj < 4; nj++) {
                    int j = nj >> 1, q = (nj & 1) * 2;
                    mma_f16(acc[mi][nj], ah[0], ah[1], ah[2], ah[3],
                            bh[j][q], bh[j][q + 1]);
                }
            }
        }
        if (lane == 0) MBAR_ARRIVE(mb_empty + (c % NB) * 8);
    }

    // ---------------- epilogue ----------------
    const int colBase = col0 + wn * 32 + (lane & 3) * 2;
#pragma unroll
    for (int mi = 0; mi < 4; mi++) {
        int r0 = row0 + wm * 64 + mi * 16 + (lane >> 2);
        int r1 = r0 + 8;
#pragma unroll
        for (int nj = 0; nj < 4; nj++) {
            int col = colBase + nj * 8;
            float b0 = bias_e ? bias_e[col] : 0.f;
            float b1 = bias_e ? bias_e[col + 1] : 0.f;
            float v00 = acc[mi][nj][0] + b0;
            float v01 = acc[mi][nj][1] + b1;
            float v10 = acc[mi][nj][2] + b0;
            float v11 = acc[mi][nj][3] + b1;
            if (doRelu) {
                v00 = fmaxf(v00, 0.f); v01 = fmaxf(v01, 0.f);
                v10 = fmaxf(v10, 0.f); v11 = fmaxf(v11, 0.f);
            }
            if (r0 < M) {
                long long o = (long long)(obase + r0) * N + col;
                if (Cf) { Cf[o] = v00; Cf[o + 1] = v01; }
                if (Oh) {
                    __half2 hv = __floats2half2_rn(v00, v01);
                    *reinterpret_cast<uint32_t*>(Oh + o) =
                        *reinterpret_cast<uint32_t*>(&hv);
                }
            }
            if (r1 < M) {
                long long o = (long long)(obase + r1) * N + col;
                if (Cf) { Cf[o] = v10; Cf[o + 1] = v11; }
                if (Oh) {
                    __half2 hv = __floats2half2_rn(v10, v11);
                    *reinterpret_cast<uint32_t*>(Oh + o) =
                        *reinterpret_cast<uint32_t*>(&hv);
                }
            }
        }
    }
}

// ---------------- launch ----------------
extern "C" void kernel_launch(void* const* d_in, const int* in_sizes, int n_in,
                              void* d_out, int out_size)
{
    const float* x      = (const float*)d_in[0];
    const float* W_in   = (const float*)d_in[1];
    const float* b_in   = (const float*)d_in[2];
    const float* W_gate = (const float*)d_in[3];
    const float* W1     = (const float*)d_in[4];
    const float* b1     = (const float*)d_in[5];
    const float* W2     = (const float*)d_in[6];
    const float* b2     = (const float*)d_in[7];
    const float* W_head = (const float*)d_in[8];
    float* out = (float*)d_out;

    float *wgp_p;
    int *cnt_p, *base_p, *bidx_p;
    int2 *tokE_p, *tokP_p;
    float2 *tokW_p;
    uint16_t *x16, *wi16, *h16, *he16, *ys16, *m16, *w1f, *w2f, *whf;
    cudaGetSymbolAddress((void**)&wgp_p, g_wgp);
    cudaGetSymbolAddress((void**)&cnt_p, g_cnt);
    cudaGetSymbolAddress((void**)&base_p,g_base);
    cudaGetSymbolAddress((void**)&bidx_p,g_bidx);
    cudaGetSymbolAddress((void**)&tokE_p,g_tokE);
    cudaGetSymbolAddress((void**)&tokP_p,g_tokP);
    cudaGetSymbolAddress((void**)&tokW_p,g_tokW);
    cudaGetSymbolAddress((void**)&x16,  g_x16);
    cudaGetSymbolAddress((void**)&wi16, g_wi16);
    cudaGetSymbolAddress((void**)&h16,  g_h16);
    cudaGetSymbolAddress((void**)&he16, g_he16);
    cudaGetSymbolAddress((void**)&ys16, g_ys16);
    cudaGetSymbolAddress((void**)&m16,  g_m16);
    cudaGetSymbolAddress((void**)&w1f,  g_w1f);
    cudaGetSymbolAddress((void**)&w2f,  g_w2f);
    cudaGetSymbolAddress((void**)&whf,  g_whf);

    const int gemm_smem = 1024 + 4 * 49152;
    cudaFuncSetAttribute(tc_gemm,
                         cudaFuncAttributeMaxDynamicSharedMemorySize, gemm_smem);

    tohalf_kernel<<<2048, 256>>>(x,    x16,  (long long)NTOK * DDIM / 4);      // 1
    tohalf_kernel<<<512,  256>>>(W_in, wi16, (long long)DDIM * DDIM / 4);      // 2
    zero_i_kernel<<<1, 32>>>(cnt_p, NEXP);                                     // 3

    // 4 (profiled): h16 = fp16(x16 @ wi16 + b_in)
    tc_gemm<<<dim3(DDIM / 128, NTOK / 256, 1), 512, gemm_smem>>>(
        x16, wi16, 0,
        nullptr, h16, b_in,
        nullptr, nullptr, nullptr, NTOK, DDIM, DDIM, 0);

    // exact fp32 gate path: Wg' = W_in@W_gate, c = b_in@W_gate
    wgp_kernel<<<129, 256>>>(W_in, b_in, W_gate, wgp_p);
    gate_kernel<<<NTOK / 8, 256>>>(x, wgp_p, cnt_p, bidx_p, tokE_p, tokP_p, tokW_p);
    prefix_kernel<<<1, 32>>>(cnt_p, base_p);

    tohalf_kernel<<<4096, 256>>>(W1, w1f, (long long)NEXP * DDIM * HDIM / 4);
    tohalf_kernel<<<4096, 256>>>(W2, w2f, (long long)NEXP * HDIM * DDIM / 4);
    tohalf_kernel<<<1024, 256>>>(W_head, whf, (long long)DDIM * DOUT / 4);

    // up: he16[base[e]+m] = relu(h16[bidx[e,m]] @ W1f[e] + b1[e])
    tc_gemm<<<dim3(HDIM / 128, NTOK / 256, NEXP), 512, gemm_smem>>>(
        h16, w1f, (size_t)DDIM * HDIM,
        nullptr, he16, b1,
        bidx_p, cnt_p, base_p, 0, HDIM, DDIM, 1);

    // down: ys16[base[e]+m] = fp16(he16 @ W2f[e] + b2[e])
    tc_gemm<<<dim3(DDIM / 128, NTOK / 256, NEXP), 512, gemm_smem>>>(
        he16, w2f, (size_t)HDIM * DDIM,
        nullptr, ys16, b2,
        nullptr, cnt_p, base_p, 0, DDIM, HDIM, 0);

    // combine (fp16 in/out) -> m16 for head
    combine_kernel<<<NTOK, 128>>>(ys16, base_p, tokE_p, tokP_p, tokW_p, m16);

    // head: out = m16 @ whf
    tc_gemm<<<dim3(DOUT / 128, NTOK / 256, 1), 512, gemm_smem>>>(
        m16, whf, 0,
        out, nullptr, nullptr,
        nullptr, nullptr, nullptr, NTOK, DOUT, DDIM, 0);
}

// round 15
// speedup vs baseline: 1.1933x; 1.0462x over previous
#include <cuda_runtime.h>
#include <cuda_bf16.h>
#include <cuda_fp16.h>
#include <cstdint>
#include <math.h>

// Problem constants
#define NTOK 16384
#define DDIM 1024
#define HDIM 4096
#define NEXP 8
#define DOUT 4096
#define NSLOT (2 * NTOK)

// ---------------- scratch (no allocations allowed) ----------------
__device__ float g_wgp[DDIM * NEXP + NEXP];
__device__ int   g_cnt[NEXP];
__device__ int   g_base[NEXP];
__device__ int   g_bidx[NEXP * NTOK];
__device__ int2  g_tokE[NTOK];
__device__ int2  g_tokP[NTOK];
__device__ float2 g_tokW[NTOK];

// fp16 planes
__device__ uint16_t g_x16[(size_t)NTOK * DDIM];
__device__ uint16_t g_wi16[(size_t)DDIM * DDIM];
__device__ uint16_t g_h16[(size_t)NTOK * DDIM];
__device__ uint16_t g_he16[(size_t)NSLOT * HDIM];
__device__ uint16_t g_ys16[(size_t)NSLOT * DDIM];
__device__ uint16_t g_m16[(size_t)NTOK * DDIM];
__device__ uint16_t g_w1f[(size_t)NEXP * DDIM * HDIM];
__device__ uint16_t g_w2f[(size_t)NEXP * HDIM * DDIM];
__device__ uint16_t g_whf[(size_t)DDIM * DOUT];

// ---------------- helpers ----------------
static __device__ __forceinline__ uint32_t smem_u32(const void* p) {
    uint32_t a;
    asm("{ .reg .u64 t; cvta.to.shared.u64 t, %1; cvt.u32.u64 %0, t; }"
        : "=r"(a) : "l"(p));
    return a;
}
static __device__ __forceinline__ void cp_async16(uint32_t dst, const void* src, int srcBytes) {
    asm volatile("cp.async.cg.shared.global [%0], [%1], %2, %3;"
                 :: "r"(dst), "l"(src), "n"(16), "r"(srcBytes) : "memory");
}
#define CP_COMMIT() asm volatile("cp.async.commit_group;" ::: "memory")
#define CP_WAIT(n)  asm volatile("cp.async.wait_group %0;" :: "n"(n) : "memory")

#define MBAR_INIT(addr, cnt) \
    asm volatile("mbarrier.init.shared.b64 [%0], %1;" :: "r"(addr), "r"(cnt) : "memory")
#define MBAR_ARRIVE(addr) \
    asm volatile("mbarrier.arrive.shared.b64 _, [%0];" :: "r"(addr) : "memory")
#define MBAR_WAIT(addr, par) do {                                                   \
    uint32_t _m = (addr); uint32_t _p = (par); uint32_t _done;                      \
    asm volatile("{\n\t.reg .pred p;\n\t"                                           \
        "mbarrier.try_wait.parity.acquire.cta.shared::cta.b64 p, [%1], %2;\n\t"     \
        "selp.b32 %0, 1, 0, p;\n\t}" : "=r"(_done) : "r"(_m), "r"(_p) : "memory");  \
    if (!_done) {                                                                    \
        asm volatile("{\n\t.reg .pred P1;\n\t"                                      \
            "WL_%=:\n\t"                                                            \
            "mbarrier.try_wait.parity.acquire.cta.shared::cta.b64 P1, [%0], %1, 0x989680;\n\t" \
            "@P1 bra.uni WD_%=;\n\t"                                                \
            "bra.uni WL_%=;\n\t"                                                    \
            "WD_%=:\n\t}" :: "r"(_m), "r"(_p) : "memory");                          \
    }                                                                                \
} while (0)

static __device__ __forceinline__ void ldsm_x4(uint32_t (&r)[4], uint32_t addr) {
    asm volatile("ldmatrix.sync.aligned.m8n8.x4.shared.b16 {%0,%1,%2,%3}, [%4];"
                 : "=r"(r[0]), "=r"(r[1]), "=r"(r[2]), "=r"(r[3]) : "r"(addr));
}
static __device__ __forceinline__ void ldsm_x4_t(uint32_t (&r)[4], uint32_t addr) {
    asm volatile("ldmatrix.sync.aligned.m8n8.x4.trans.shared.b16 {%0,%1,%2,%3}, [%4];"
                 : "=r"(r[0]), "=r"(r[1]), "=r"(r[2]), "=r"(r[3]) : "r"(addr));
}
static __device__ __forceinline__ void mma_f16(float (&d)[4],
    uint32_t a0, uint32_t a1, uint32_t a2, uint32_t a3, uint32_t b0, uint32_t b1)
{
    asm volatile("mma.sync.aligned.m16n8k16.row.col.f32.f16.f16.f32 "
                 "{%0,%1,%2,%3}, {%4,%5,%6,%7}, {%8,%9}, {%0,%1,%2,%3};"
                 : "+f"(d[0]), "+f"(d[1]), "+f"(d[2]), "+f"(d[3])
                 : "r"(a0), "r"(a1), "r"(a2), "r"(a3), "r"(b0), "r"(b1));
}

// ---------------- small kernels ----------------
__global__ void zero_i_kernel(int* p, int n) {
    int i = blockIdx.x * blockDim.x + threadIdx.x;
    if (i < n) p[i] = 0;
}
__global__ void tohalf_kernel(const float* __restrict__ src,
                              uint16_t* __restrict__ dst, long long n4)
{
    long long i = blockIdx.x * (long long)blockDim.x + threadIdx.x;
    long long stride = (long long)gridDim.x * blockDim.x;
    for (; i < n4; i += stride) {
        float4 v = reinterpret_cast<const float4*>(src)[i];
        __half2 a = __floats2half2_rn(v.x, v.y);
        __half2 b = __floats2half2_rn(v.z, v.w);
        reinterpret_cast<uint2*>(dst)[i] =
            make_uint2(*reinterpret_cast<uint32_t*>(&a),
                       *reinterpret_cast<uint32_t*>(&b));
    }
}
__global__ void prefix_kernel(const int* __restrict__ cnt, int* __restrict__ base) {
    if (threadIdx.x == 0) {
        int s = 0;
#pragma unroll
        for (int e = 0; e < NEXP; e++) { base[e] = s; s += cnt[e]; }
    }
}
__global__ void __launch_bounds__(128)
combine_kernel(const uint16_t* __restrict__ ys16, const int* __restrict__ base,
               const int2* __restrict__ tokE, const int2* __restrict__ tokP,
               const float2* __restrict__ tokW, uint16_t* __restrict__ m16)
{
    const int t = blockIdx.x;
    int2 te = tokE[t];
    int2 tp = tokP[t];
    float2 tw = tokW[t];
    long long s0 = (long long)(base[te.x] + tp.x) * DDIM;
    long long s1 = (long long)(base[te.y] + tp.y) * DDIM;
    int c = threadIdx.x * 8;
    uint4 y0 = *reinterpret_cast<const uint4*>(ys16 + s0 + c);
    uint4 y1 = *reinterpret_cast<const uint4*>(ys16 + s1 + c);
    __half2 w0 = __float2half2_rn(tw.x);
    __half2 w1 = __float2half2_rn(tw.y);
    uint4 o;
    const __half2* p0 = reinterpret_cast<const __half2*>(&y0);
    const __half2* p1 = reinterpret_cast<const __half2*>(&y1);
    __half2* po = reinterpret_cast<__half2*>(&o);
#pragma unroll
    for (int j = 0; j < 4; j++)
        po[j] = __hfma2(w0, p0[j], __hmul2(w1, p1[j]));
    *reinterpret_cast<uint4*>(m16 + (long long)t * DDIM + c) = o;
}

// ---------------- Wg' = W_in @ W_gate (+ c = b_in @ W_gate), exact fp32 ----------------
__global__ void __launch_bounds__(256)
wgp_kernel(const float* __restrict__ W_in, const float* __restrict__ b_in,
           const float* __restrict__ Wg, float* __restrict__ wgp)
{
    __shared__ float sWg[DDIM * 9];
    const int tid = threadIdx.x;
    for (int i = tid; i < DDIM * NEXP; i += 256)
        sWg[(i >> 3) * 9 + (i & 7)] = Wg[i];
    __syncthreads();

    const int warp = tid >> 5;
    const int lane = tid & 31;
    const int d = blockIdx.x * 8 + warp;
    if (d > DDIM) return;

    const float* row = (d < DDIM) ? W_in + (long long)d * DDIM : b_in;

    float accv[NEXP];
#pragma unroll
    for (int e = 0; e < NEXP; e++) accv[e] = 0.f;
    for (int j = lane; j < DDIM; j += 32) {
        float v = row[j];
        const float* wr = &sWg[j * 9];
#pragma unroll
        for (int e = 0; e < NEXP; e++)
            accv[e] = fmaf(v, wr[e], accv[e]);
    }
#pragma unroll
    for (int e = 0; e < NEXP; e++) {
#pragma unroll
        for (int off = 16; off > 0; off >>= 1)
            accv[e] += __shfl_xor_sync(0xffffffffu, accv[e], off);
    }
    if (lane == 0) {
#pragma unroll
        for (int e = 0; e < NEXP; e++)
            wgp[d * NEXP + e] = accv[e];
    }
}

// ---------------- gating: exact fp32 logits from x ----------------
__global__ void __launch_bounds__(256)
gate_kernel(const float* __restrict__ x, const float* __restrict__ wgp,
            int* __restrict__ cnt, int* __restrict__ bidx,
            int2* __restrict__ tokE, int2* __restrict__ tokP,
            float2* __restrict__ tokW)
{
    __shared__ float sW[DDIM * 9];
    __shared__ float sc[NEXP];
    const int tid = threadIdx.x;
    for (int i = tid; i < DDIM * NEXP; i += 256)
        sW[(i >> 3) * 9 + (i & 7)] = wgp[i];
    if (tid < NEXP) sc[tid] = wgp[DDIM * NEXP + tid];
    __syncthreads();

    const int warp = tid >> 5;
    const int lane = tid & 31;
    const int token = blockIdx.x * 8 + warp;
    if (token >= NTOK) return;

    float accv[NEXP];
#pragma unroll
    for (int e = 0; e < NEXP; e++) accv[e] = 0.f;
    const float* xrow = x + (long long)token * DDIM;
    for (int d = lane; d < DDIM; d += 32) {
        float xv = xrow[d];
        const float* wr = &sW[d * 9];
#pragma unroll
        for (int e = 0; e < NEXP; e++)
            accv[e] = fmaf(xv, wr[e], accv[e]);
    }
#pragma unroll
    for (int e = 0; e < NEXP; e++) {
#pragma unroll
        for (int off = 16; off > 0; off >>= 1)
            accv[e] += __shfl_xor_sync(0xffffffffu, accv[e], off);
    }
    if (lane == 0) {
#pragma unroll
        for (int e = 0; e < NEXP; e++) accv[e] += sc[e];
        int i1 = 0; float l1 = accv[0];
#pragma unroll
        for (int e = 1; e < NEXP; e++)
            if (accv[e] > l1) { l1 = accv[e]; i1 = e; }
        int i2 = -1; float l2 = -3.0e38f;
#pragma unroll
        for (int e = 0; e < NEXP; e++)
            if (e != i1 && accv[e] > l2) { l2 = accv[e]; i2 = e; }
        float p2 = expf(l2 - l1);
        float w1 = 1.f / (1.f + p2);
        float w2 = p2 * w1;
        int p = atomicAdd(&cnt[i1], 1);
        bidx[i1 * NTOK + p] = token;
        int q = atomicAdd(&cnt[i2], 1);
        bidx[i2 * NTOK + q] = token;
        tokE[token] = make_int2(i1, i2);
        tokP[token] = make_int2(p, q);
        tokW[token] = make_float2(w1, w2);
    }
}

// ---------------- warp-specialized fp16 GEMM ----------------
// Tile 192x128, 448 threads: warps 0..11 consumers (3x4 of 64x32),
// warps 12..13 producers (all cp.async). CK=64, NB=4 buffers.
#define TM 192
#define GEMM_THREADS 448
#define GEMM_SMEM (1024 + 4 * 40960)

__global__ void __launch_bounds__(GEMM_THREADS, 1)
tc_gemm(const uint16_t* __restrict__ A_g, const uint16_t* __restrict__ B_g,
        size_t bStride,
        float* __restrict__ Cf, uint16_t* __restrict__ Oh,
        const float* __restrict__ bias,
        const int* __restrict__ gatherIdx,
        const int* __restrict__ cntPtr, const int* __restrict__ basePtr,
        int Mfix, int N, int K, int doRelu)
{
    extern __shared__ char smem[];

    constexpr int CK   = 64;
    constexpr int NB   = 4;
    constexpr uint32_t ARB  = 128;                // A row bytes
    constexpr uint32_t BOFF = TM * ARB;           // 24576
    constexpr uint32_t BUFB = BOFF + 16384;       // 40960

    const int z = blockIdx.z;
    int M = cntPtr ? __ldg(cntPtr + z) : Mfix;
    const int obase = basePtr ? __ldg(basePtr + z) : 0;
    const int row0 = blockIdx.y * TM;
    if (row0 >= M) return;
    const int col0 = blockIdx.x * 128;

    const int tid  = threadIdx.x;
    const int lane = tid & 31;
    const int wid  = tid >> 5;      // 0..13

    const uint32_t smem_base = smem_u32(smem);
    const uint32_t mb_full  = smem_base;
    const uint32_t mb_empty = smem_base + 64;
    int* gRow_s = reinterpret_cast<int*>(smem + 128);   // [TM]
    const uint32_t tiles    = smem_base + 1024;

    const int* gIdx = gatherIdx ? gatherIdx + (size_t)z * NTOK : nullptr;

    if (tid == 0) {
#pragma unroll
        for (int b = 0; b < NB; b++) {
            MBAR_INIT(mb_full + b * 8, 64);    // all 64 producer threads arrive
            MBAR_INIT(mb_empty + b * 8, 12);   // 12 consumer lane0s arrive
        }
    }
    if (tid < TM) {
        int m = row0 + tid;
        gRow_s[tid] = (m < M) ? (gIdx ? gIdx[m] : obase + m) : -1;
    }
    __syncthreads();

    const uint16_t* B_e = B_g + (size_t)z * bStride;
    const int nchunk = K / CK;

    // =========== producers ===========
    if (wid >= 12) {
        const int ptid = tid - 384;          // 0..63
        const int rowBase = ptid >> 3;       // 0..7
        const int colA = ptid & 7;
        const uint32_t swA = (uint32_t)(colA ^ rowBase) << 4;
        int gr[24];
#pragma unroll
        for (int i = 0; i < 24; i++) gr[i] = gRow_s[rowBase + 8 * i];

        for (int c = 0; c < nchunk; c++) {
            int b = c % NB;
            if (c >= NB) MBAR_WAIT(mb_empty + b * 8, ((c - NB) / NB) & 1);
            int k0 = c * CK;
            uint32_t bufA = tiles + b * BUFB;
            uint32_t bufB = bufA + BOFF;
#pragma unroll
            for (int i = 0; i < 24; i++) {
                uint32_t d = bufA + (uint32_t)(rowBase + 8 * i) * ARB + swA;
                const uint16_t* s = (gr[i] >= 0)
                    ? A_g + (long long)gr[i] * K + k0 + colA * 8 : A_g;
                cp_async16(d, s, (gr[i] >= 0) ? 16 : 0);
            }
#pragma unroll
            for (int i = 0; i < 16; i++) {
                int u = ptid + 64 * i;
                int kr = u >> 4, un = u & 15;
                uint32_t d = bufB + kr * 256 + (((uint32_t)(un ^ (kr & 7))) << 4);
                cp_async16(d, B_e + (long long)(k0 + kr) * N + col0 + un * 8, 16);
            }
            CP_COMMIT();
            if (c >= 2) { CP_WAIT(2); MBAR_ARRIVE(mb_full + ((c - 2) % NB) * 8); }
        }
        CP_WAIT(1); MBAR_ARRIVE(mb_full + ((nchunk - 2) % NB) * 8);
        CP_WAIT(0); MBAR_ARRIVE(mb_full + ((nchunk - 1) % NB) * 8);
        return;
    }

    // =========== consumers ===========
    const int wm = wid >> 2;       // 0..2
    const int wn = wid & 3;        // 0..3

    const int rowA  = wm * 64 + (lane & 7) + ((lane >> 3) & 1) * 8;
    const int kbA   = (lane >> 4) & 1;
    const int swzA  = rowA & 7;
    const int kBld  = (lane & 7) + ((lane >> 3) & 1) * 8;
    const int nbB   = (lane >> 4) & 1;
    const int kswzB = kBld & 7;
    const int krot  = wid & 3;     // per-warp kstep rotation

    float acc[4][4][4];
#pragma unroll
    for (int mi = 0; mi < 4; mi++)
#pragma unroll
        for (int nj = 0; nj < 4; nj++)
#pragma unroll
            for (int q = 0; q < 4; q++) acc[mi][nj][q] = 0.f;

    for (int c = 0; c < nchunk; c++) {
        const int b = c % NB;
        MBAR_WAIT(mb_full + b * 8, (c / NB) & 1);
        const uint32_t bufA = tiles + b * BUFB;
        const uint32_t bufB = bufA + BOFF;

#pragma unroll
        for (int ks = 0; ks < 4; ks++) {
            const int kk = (ks + krot) & 3;
            uint32_t bh[2][4];
#pragma unroll
            for (int j = 0; j < 2; j++) {
                int nchk = wn * 4 + j * 2 + nbB;
                uint32_t boff = (uint32_t)((kBld + kk * 16) * 256 +
                                ((nchk ^ kswzB) << 4));
                ldsm_x4_t(bh[j], bufB + boff);
            }
#pragma unroll
            for (int mi = 0; mi < 4; mi++) {
                uint32_t ah[4];
                uint32_t aoff = (uint32_t)((rowA + mi * 16) * ARB +
                                (((kk * 2 + kbA) ^ swzA) << 4));
                ldsm_x4(ah, bufA + aoff);
#pragma unroll
                for (int nj = 0; nj < 4; nj++) {
                    int j = nj >> 1, q = (nj & 1) * 2;
                    mma_f16(acc[mi][nj], ah[0], ah[1], ah[2], ah[3],
                            bh[j][q], bh[j][q + 1]);
                }
            }
        }
        __syncwarp();
        if (lane == 0) MBAR_ARRIVE(mb_empty + b * 8);
    }

    // ---------------- epilogue ----------------
    const float* bias_e = bias ? bias + (size_t)z * N : nullptr;
    const int colBase = col0 + wn * 32 + (lane & 3) * 2;
#pragma unroll
    for (int mi = 0; mi < 4; mi++) {
        int r0 = row0 + wm * 64 + mi * 16 + (lane >> 2);
        int r1 = r0 + 8;
#pragma unroll
        for (int nj = 0; nj < 4; nj++) {
            int col = colBase + nj * 8;
            float b0 = bias_e ? bias_e[col] : 0.f;
            float b1 = bias_e ? bias_e[col + 1] : 0.f;
            float v00 = acc[mi][nj][0] + b0;
            float v01 = acc[mi][nj][1] + b1;
            float v10 = acc[mi][nj][2] + b0;
            float v11 = acc[mi][nj][3] + b1;
            if (doRelu) {
                v00 = fmaxf(v00, 0.f); v01 = fmaxf(v01, 0.f);
                v10 = fmaxf(v10, 0.f); v11 = fmaxf(v11, 0.f);
            }
            if (r0 < M) {
                long long o = (long long)(obase + r0) * N + col;
                if (Cf) { Cf[o] = v00; Cf[o + 1] = v01; }
                if (Oh) {
                    __half2 hv = __floats2half2_rn(v00, v01);
                    *reinterpret_cast<uint32_t*>(Oh + o) =
                        *reinterpret_cast<uint32_t*>(&hv);
                }
            }
            if (r1 < M) {
                long long o = (long long)(obase + r1) * N + col;
                if (Cf) { Cf[o] = v10; Cf[o + 1] = v11; }
                if (Oh) {
                    __half2 hv = __floats2half2_rn(v10, v11);
                    *reinterpret_cast<uint32_t*>(Oh + o) =
                        *reinterpret_cast<uint32_t*>(&hv);
                }
            }
        }
    }
}

#define GEMM_YT ((NTOK + TM - 1) / TM)   // 86 row tiles cover any M <= NTOK

// ---------------- launch ----------------
extern "C" void kernel_launch(void* const* d_in, const int* in_sizes, int n_in,
                              void* d_out, int out_size)
{
    const float* x      = (const float*)d_in[0];
    const float* W_in   = (const float*)d_in[1];
    const float* b_in   = (const float*)d_in[2];
    const float* W_gate = (const float*)d_in[3];
    const float* W1     = (const float*)d_in[4];
    const float* b1     = (const float*)d_in[5];
    const float* W2     = (const float*)d_in[6];
    const float* b2     = (const float*)d_in[7];
    const float* W_head = (const float*)d_in[8];
    float* out = (float*)d_out;

    float *wgp_p;
    int *cnt_p, *base_p, *bidx_p;
    int2 *tokE_p, *tokP_p;
    float2 *tokW_p;
    uint16_t *x16, *wi16, *h16, *he16, *ys16, *m16, *w1f, *w2f, *whf;
    cudaGetSymbolAddress((void**)&wgp_p, g_wgp);
    cudaGetSymbolAddress((void**)&cnt_p, g_cnt);
    cudaGetSymbolAddress((void**)&base_p,g_base);
    cudaGetSymbolAddress((void**)&bidx_p,g_bidx);
    cudaGetSymbolAddress((void**)&tokE_p,g_tokE);
    cudaGetSymbolAddress((void**)&tokP_p,g_tokP);
    cudaGetSymbolAddress((void**)&tokW_p,g_tokW);
    cudaGetSymbolAddress((void**)&x16,  g_x16);
    cudaGetSymbolAddress((void**)&wi16, g_wi16);
    cudaGetSymbolAddress((void**)&h16,  g_h16);
    cudaGetSymbolAddress((void**)&he16, g_he16);
    cudaGetSymbolAddress((void**)&ys16, g_ys16);
    cudaGetSymbolAddress((void**)&m16,  g_m16);
    cudaGetSymbolAddress((void**)&w1f,  g_w1f);
    cudaGetSymbolAddress((void**)&w2f,  g_w2f);
    cudaGetSymbolAddress((void**)&whf,  g_whf);

    cudaFuncSetAttribute(tc_gemm,
                         cudaFuncAttributeMaxDynamicSharedMemorySize, GEMM_SMEM);

    tohalf_kernel<<<2048, 256>>>(x,    x16,  (long long)NTOK * DDIM / 4);      // 1
    tohalf_kernel<<<512,  256>>>(W_in, wi16, (long long)DDIM * DDIM / 4);      // 2
    zero_i_kernel<<<1, 32>>>(cnt_p, NEXP);                                     // 3

    // 4 (profiled): h16 = fp16(x16 @ wi16 + b_in)
    tc_gemm<<<dim3(DDIM / 128, GEMM_YT, 1), GEMM_THREADS, GEMM_SMEM>>>(
        x16, wi16, 0,
        nullptr, h16, b_in,
        nullptr, nullptr, nullptr, NTOK, DDIM, DDIM, 0);

    // exact fp32 gate path
    wgp_kernel<<<129, 256>>>(W_in, b_in, W_gate, wgp_p);
    gate_kernel<<<NTOK / 8, 256>>>(x, wgp_p, cnt_p, bidx_p, tokE_p, tokP_p, tokW_p);
    prefix_kernel<<<1, 32>>>(cnt_p, base_p);

    tohalf_kernel<<<4096, 256>>>(W1, w1f, (long long)NEXP * DDIM * HDIM / 4);
    tohalf_kernel<<<4096, 256>>>(W2, w2f, (long long)NEXP * HDIM * DDIM / 4);
    tohalf_kernel<<<1024, 256>>>(W_head, whf, (long long)DDIM * DOUT / 4);

    // up: he16[base[e]+m] = relu(h16[bidx[e,m]] @ W1f[e] + b1[e])
    tc_gemm<<<dim3(HDIM / 128, GEMM_YT, NEXP), GEMM_THREADS, GEMM_SMEM>>>(
        h16, w1f, (size_t)DDIM * HDIM,
        nullptr, he16, b1,
        bidx_p, cnt_p, base_p, 0, HDIM, DDIM, 1);

    // down: ys16[base[e]+m] = fp16(he16 @ W2f[e] + b2[e])
    tc_gemm<<<dim3(DDIM / 128, GEMM_YT, NEXP), GEMM_THREADS, GEMM_SMEM>>>(
        he16, w2f, (size_t)HDIM * DDIM,
        nullptr, ys16, b2,
        nullptr, cnt_p, base_p, 0, DDIM, HDIM, 0);

    // combine (fp16 in/out) -> m16 for head
    combine_kernel<<<NTOK, 128>>>(ys16, base_p, tokE_p, tokP_p, tokW_p, m16);

    // head: out = m16 @ whf
    tc_gemm<<<dim3(DOUT / 128, GEMM_YT, 1), GEMM_THREADS, GEMM_SMEM>>>(
        m16, whf, 0,
        out, nullptr, nullptr,
        nullptr, nullptr, nullptr, NTOK, DOUT, DDIM, 0);
}